// round 15
// baseline (speedup 1.0000x reference)
#include <cuda_runtime.h>
#include <math.h>

// ---------------- problem constants (fixed shapes) ----------------
#define BB   2
#define NN   21952          // 28^3
#define CC   96
#define BNr  43904          // BB*NN
#define NH2  3
#define NSR  343            // 7^3
#define WT   343
#define NWIN 64

typedef unsigned long long u64;

__device__ __forceinline__ u64 ffma2(u64 a, u64 b, u64 c) {
    u64 d; asm("fma.rn.f32x2 %0,%1,%2,%3;" : "=l"(d) : "l"(a), "l"(b), "l"(c)); return d;
}
__device__ __forceinline__ u64 fadd2(u64 a, u64 b) {
    u64 d; asm("add.rn.f32x2 %0,%1,%2;" : "=l"(d) : "l"(a), "l"(b)); return d;
}
__device__ __forceinline__ u64 pack2(float x, float y) {
    u64 d; asm("mov.b64 %0,{%1,%2};" : "=l"(d) : "f"(x), "f"(y)); return d;
}
__device__ __forceinline__ float2 unpack2(u64 a) {
    float2 f; asm("mov.b64 {%0,%1},%2;" : "=f"(f.x), "=f"(f.y) : "l"(a)); return f;
}
__device__ __forceinline__ float ex2f(float x) {
    float r; asm("ex2.approx.f32 %0, %1;" : "=f"(r) : "f"(x)); return r;
}
#define D2U(x) __double_as_longlong(x)
#define QSCALE (0.25f * 1.4426950408889634f)

// ---------------- device scratch ----------------
__device__ float  g_t   [BNr*CC];
__device__ float  g_lepe[BNr*CC];
__device__ float  g_q12 [BNr*CC];
__device__ float  g_kv2 [BNr*CC];
__device__ float  g_xs  [BB*NSR*CC];
__device__ float  g_kv1 [BB*NSR*CC];
__device__ float  g_xcat[BNr*CC];
__device__ float2 g_wtp [64*48*CC];

// ---------------- fused x-projections: t (bias), q12, kv2 in one kernel ----------------
__global__ __launch_bounds__(256) void gemm_x3_kernel(
    const float* __restrict__ x,
    const float* __restrict__ lepe_lin_w, const float* __restrict__ lepe_lin_b,
    const float* __restrict__ q1_w, const float* __restrict__ q2_w,
    const float* __restrict__ kv2_w,
    float* __restrict__ t_out, float* __restrict__ q12_out, float* __restrict__ kv2_out)
{
    extern __shared__ float sm[];
    float*  As = sm;                        // [64][96]
    float4* Wq = (float4*)(sm + 64*CC);     // [24][100]
    const int tid = threadIdx.x;
    const int m0  = blockIdx.x * 64;

    for (int i = tid; i < 64*CC; i += 256)
        As[i] = x[(size_t)m0*CC + i];

    const int ty = tid >> 4, tx = tid & 15;
    const int mb = ty*4;

#pragma unroll
    for (int pass = 0; pass < 3; pass++) {
        for (int i = tid; i < 24*CC; i += 256) {
            int k4 = i / CC, j = i - k4*CC;
            const float* Wr;
            if (pass == 0)      Wr = lepe_lin_w + (size_t)j*CC;
            else if (pass == 1) Wr = (j < 48) ? (q1_w + (size_t)j*CC) : (q2_w + (size_t)(j-48)*CC);
            else                Wr = kv2_w + (size_t)j*CC;
            Wq[k4*100 + j] = *(const float4*)(Wr + 4*k4);
        }
        __syncthreads();

        u64 acc[4][6];
#pragma unroll
        for (int r = 0; r < 4; r++)
#pragma unroll
            for (int j = 0; j < 6; j++) acc[r][j] = 0ull;

#pragma unroll 4
        for (int k4 = 0; k4 < 24; k4++) {
            double2 a[4];
#pragma unroll
            for (int r = 0; r < 4; r++) a[r] = *(const double2*)(As + (mb+r)*CC + k4*4);
            double2 w[6];
#pragma unroll
            for (int j = 0; j < 6; j++) w[j] = *(const double2*)(Wq + k4*100 + tx + 16*j);
#pragma unroll
            for (int r = 0; r < 4; r++)
#pragma unroll
                for (int j = 0; j < 6; j++) {
                    acc[r][j] = ffma2(D2U(a[r].x), D2U(w[j].x), acc[r][j]);
                    acc[r][j] = ffma2(D2U(a[r].y), D2U(w[j].y), acc[r][j]);
                }
        }

        float* outp = (pass == 0) ? t_out : (pass == 1 ? q12_out : kv2_out);
#pragma unroll
        for (int r = 0; r < 4; r++) {
            int gr = m0 + mb + r;
#pragma unroll
            for (int j = 0; j < 6; j++) {
                int col = tx + 16*j;
                float2 f = unpack2(acc[r][j]);
                float o = f.x + f.y;
                if (pass == 0) o += lepe_lin_b[col];
                outp[(size_t)gr*CC + col] = o;
            }
        }
        __syncthreads();
    }
}

// ---------------- f32x2 GEMM (proj: xcat+lepe -> out) ----------------
__global__ __launch_bounds__(256) void gemm_proj_kernel(
    const float* __restrict__ A, const float* __restrict__ A2,
    const float* __restrict__ W1, const float* __restrict__ bias,
    float* __restrict__ out)
{
    extern __shared__ float sm[];
    float*  As = sm;
    float4* Wq = (float4*)(sm + 64*CC);
    const int tid = threadIdx.x;
    const int m0  = blockIdx.x * 64;

    for (int i = tid; i < 64*CC; i += 256)
        As[i] = A[(size_t)m0*CC + i] + A2[(size_t)m0*CC + i];
    for (int i = tid; i < 24*CC; i += 256) {
        int k4 = i / CC, j = i - k4*CC;
        Wq[k4*100 + j] = *(const float4*)(W1 + (size_t)j*CC + 4*k4);
    }
    __syncthreads();

    const int ty = tid >> 4, tx = tid & 15;
    const int mb = ty*4;
    u64 acc[4][6];
#pragma unroll
    for (int r = 0; r < 4; r++)
#pragma unroll
        for (int j = 0; j < 6; j++) acc[r][j] = 0ull;

#pragma unroll 4
    for (int k4 = 0; k4 < 24; k4++) {
        double2 a[4];
#pragma unroll
        for (int r = 0; r < 4; r++) a[r] = *(const double2*)(As + (mb+r)*CC + k4*4);
        double2 w[6];
#pragma unroll
        for (int j = 0; j < 6; j++) w[j] = *(const double2*)(Wq + k4*100 + tx + 16*j);
#pragma unroll
        for (int r = 0; r < 4; r++)
#pragma unroll
            for (int j = 0; j < 6; j++) {
                acc[r][j] = ffma2(D2U(a[r].x), D2U(w[j].x), acc[r][j]);
                acc[r][j] = ffma2(D2U(a[r].y), D2U(w[j].y), acc[r][j]);
            }
    }

#pragma unroll
    for (int r = 0; r < 4; r++) {
        int gr = m0 + mb + r;
#pragma unroll
        for (int j = 0; j < 6; j++) {
            int col = tx + 16*j;
            float2 f = unpack2(acc[r][j]);
            out[(size_t)gr*CC + col] = f.x + f.y + bias[col];
        }
    }
}

// ---------------- LePE depthwise 3x3x3 ----------------
__global__ __launch_bounds__(192) void lepe_conv_kernel(
    const float* __restrict__ tin, const float* __restrict__ cw,
    const float* __restrict__ cb, float* __restrict__ out)
{
    __shared__ float st [216*24];
    __shared__ float wst[27*24];
    const int tid = threadIdx.x;
    const int b = blockIdx.x / 343;
    const int t = blockIdx.x % 343;
    const int c0 = blockIdx.y * 24;
    const int th = t / 49, tw = (t / 7) % 7, td = t % 7;
    const int h0 = th*4 - 1, w0 = tw*4 - 1, d0 = td*4 - 1;

    for (int i = tid; i < 216*6; i += 192) {
        int hv = i / 6, cq = (i - hv*6) * 4;
        int lz = hv / 36, ly = (hv / 6) % 6, lx = hv % 6;
        int gz = h0 + lz, gy = w0 + ly, gx = d0 + lx;
        float4 v = make_float4(0.f, 0.f, 0.f, 0.f);
        if ((unsigned)gz < 28u && (unsigned)gy < 28u && (unsigned)gx < 28u)
            v = *(const float4*)(tin + ((size_t)b*NN + gz*784 + gy*28 + gx)*CC + c0 + cq);
        *(float4*)(st + hv*24 + cq) = v;
    }
    for (int i = tid; i < 27*24; i += 192) {
        int cl = i / 27, j = i - cl*27;
        wst[j*24 + cl] = cw[(c0 + cl)*27 + j];
    }
    __syncthreads();

    const int half = tid / 96;
    const int t96 = tid - half*96;
    const int hw = t96 / 6;
    const int c4 = (t96 - hw*6) * 4;
    const int lh = hw >> 2, lw = hw & 3;
    const int dbase = half*2;

    u64 acc[2][2];
    {
        double2 cbv = *(const double2*)(cb + c0 + c4);
#pragma unroll
        for (int v = 0; v < 2; v++) { acc[v][0] = D2U(cbv.x); acc[v][1] = D2U(cbv.y); }
    }

#pragma unroll
    for (int jz = 0; jz < 3; jz++)
#pragma unroll
        for (int jy = 0; jy < 3; jy++) {
            const int base = (lh + jz)*36 + (lw + jy)*6 + dbase;
            double2 col[4];
#pragma unroll
            for (int dd = 0; dd < 4; dd++) col[dd] = *(const double2*)(st + (base + dd)*24 + c4);
#pragma unroll
            for (int jx = 0; jx < 3; jx++) {
                double2 wv = *(const double2*)(wst + (jz*9 + jy*3 + jx)*24 + c4);
                u64 w0v = D2U(wv.x), w1v = D2U(wv.y);
#pragma unroll
                for (int vd = 0; vd < 2; vd++) {
                    acc[vd][0] = ffma2(D2U(col[vd+jx].x), w0v, acc[vd][0]);
                    acc[vd][1] = ffma2(D2U(col[vd+jx].y), w1v, acc[vd][1]);
                }
            }
        }

#pragma unroll
    for (int vd = 0; vd < 2; vd++) {
        int n = (th*4 + lh)*784 + (tw*4 + lw)*28 + (td*4 + dbase + vd);
        float2 f0 = unpack2(acc[vd][0]), f1 = unpack2(acc[vd][1]);
        *(float4*)(out + ((size_t)b*NN + n)*CC + c0 + c4) = make_float4(f0.x, f0.y, f1.x, f1.y);
    }
}

// ---------------- pack SR weights (coalesced) + init xs with bias ----------------
__global__ __launch_bounds__(256) void sr_pack_init_kernel(
    const float* __restrict__ w, const float* __restrict__ srb,
    float2* __restrict__ wtp, float* __restrict__ xs)
{
    int i = blockIdx.x * 256 + threadIdx.x;
    if (i < 64*48*CC) {
        int v = i & 63;
        int rem = i >> 6;
        int j = rem % CC;
        int k2 = rem / CC;
        float a = w[((size_t)j*CC + 2*k2  )*64 + v];
        float b = w[((size_t)j*CC + 2*k2+1)*64 + v];
        wtp[(size_t)v*48*CC + k2*CC + j] = make_float2(a, b);
    }
    if (i < BB*NSR*CC) xs[i] = srb[i % CC];
}

// ---------------- SR conv: 32-row tile, 4x6 thread tile, 128 thr, 4 voxels/block ----------------
__global__ __launch_bounds__(128) void sr_conv_kernel(
    const float* __restrict__ x, const float2* __restrict__ wtp,
    float* __restrict__ xs)
{
    extern __shared__ float sm[];
    float*  As  = sm;                       // [32][96]
    float4* Wp4 = (float4*)(sm + 32*CC);    // [48][49] float4
    const int tid = threadIdx.x;
    const int m0 = blockIdx.x * 32;
    const int v0 = blockIdx.y * 4;
    const int ty = tid >> 4, tx = tid & 15;
    const int mb = ty*4;

    // per-thread staged row quarter (hoisted)
    const int r8 = tid >> 2;       // 0..31
    const int l8 = tid & 3;        // 0..3, 24 floats each
    const int gr8 = m0 + r8;
    const float* xrow = x;
    int hh4 = 0, ww4 = 0, dd4 = 0;
    const bool valid = gr8 < BB*NSR;
    if (valid) {
        int b = gr8 / NSR, p = gr8 - b*NSR;
        int ph = p / 49, pr = p - ph*49;
        int pw = pr / 7, pd = pr - pw*7;
        xrow = x + (size_t)b*NN*CC;
        hh4 = 4*ph; ww4 = 4*pw; dd4 = 4*pd;
    }

    u64 acc[4][6];
#pragma unroll
    for (int r = 0; r < 4; r++)
#pragma unroll
        for (int j = 0; j < 6; j++) acc[r][j] = 0ull;

    for (int vv = 0; vv < 4; vv++) {
        const int v = v0 + vv;
        const int kh = v >> 4, kw = (v >> 2) & 3, kd = v & 3;

        // stage As: 6 float4 per thread
        {
            float4* dst = (float4*)(As + r8*CC + l8*24);
            if (valid) {
                const float* src = xrow + ((size_t)((hh4+kh)*784 + (ww4+kw)*28 + (dd4+kd)))*CC + l8*24;
#pragma unroll
                for (int q = 0; q < 6; q++) dst[q] = *(const float4*)(src + 4*q);
            } else {
                float4 z = make_float4(0.f,0.f,0.f,0.f);
#pragma unroll
                for (int q = 0; q < 6; q++) dst[q] = z;
            }
        }
        // stage Wp4: 18 float4 per thread
        for (int i = tid; i < 48*48; i += 128) {
            int k2 = i / 48, j4 = i - k2*48;
            Wp4[k2*49 + j4] = *(const float4*)(&wtp[(size_t)v*48*CC + k2*CC + 2*j4]);
        }
        __syncthreads();

#pragma unroll 2
        for (int k4 = 0; k4 < 24; k4++) {
            double2 a[4];
#pragma unroll
            for (int r = 0; r < 4; r++) a[r] = *(const double2*)(As + (mb+r)*CC + k4*4);
            const float4* wra = Wp4 + (2*k4  )*49 + tx*3;
            const float4* wrb = Wp4 + (2*k4+1)*49 + tx*3;
#pragma unroll
            for (int jj = 0; jj < 3; jj++) {
                float4 wa = wra[jj];
                float4 wb = wrb[jj];
                u64 wa0 = ((const u64*)&wa)[0], wa1 = ((const u64*)&wa)[1];
                u64 wb0 = ((const u64*)&wb)[0], wb1 = ((const u64*)&wb)[1];
#pragma unroll
                for (int r = 0; r < 4; r++) {
                    acc[r][jj*2+0] = ffma2(D2U(a[r].x), wa0, acc[r][jj*2+0]);
                    acc[r][jj*2+1] = ffma2(D2U(a[r].x), wa1, acc[r][jj*2+1]);
                    acc[r][jj*2+0] = ffma2(D2U(a[r].y), wb0, acc[r][jj*2+0]);
                    acc[r][jj*2+1] = ffma2(D2U(a[r].y), wb1, acc[r][jj*2+1]);
                }
            }
        }
        __syncthreads();
    }

#pragma unroll
    for (int r = 0; r < 4; r++) {
        int gr = m0 + mb + r;
        if (gr >= BB*NSR) continue;
#pragma unroll
        for (int j = 0; j < 6; j++) {
            float2 f = unpack2(acc[r][j]);
            atomicAdd(&xs[(size_t)gr*CC + tx*6 + j], f.x + f.y);
        }
    }
}

// ---------------- LayerNorm + GELU + kv1 GEMM (4 rows / block) ----------------
__global__ __launch_bounds__(96) void ln_gelu_kv1_kernel(
    const float* __restrict__ xs, const float* __restrict__ gg,
    const float* __restrict__ bb, const float* __restrict__ w,
    float* __restrict__ kv)
{
    __shared__ float ws[CC*98];
    __shared__ float row[CC];
    __shared__ float rs[3], rs2[3];
    const int tid = threadIdx.x;

    for (int i = tid; i < CC*CC; i += 96)
        ws[(i / CC)*98 + (i % CC)] = w[i];

    for (int rr = 0; rr < 4; rr++) {
        int r = blockIdx.x*4 + rr;
        if (r >= BB*NSR) break;
        __syncthreads();
        float v = xs[(size_t)r*CC + tid];
        float s = v, s2 = v*v;
#pragma unroll
        for (int o = 16; o; o >>= 1) {
            s  += __shfl_xor_sync(0xffffffffu, s, o);
            s2 += __shfl_xor_sync(0xffffffffu, s2, o);
        }
        if ((tid & 31) == 0) { rs[tid >> 5] = s; rs2[tid >> 5] = s2; }
        __syncthreads();
        float mean = (rs[0] + rs[1] + rs[2]) * (1.f/96.f);
        float var  = (rs2[0] + rs2[1] + rs2[2]) * (1.f/96.f) - mean*mean;
        float xn = (v - mean) * rsqrtf(var + 1e-5f) * gg[tid] + bb[tid];
        row[tid] = 0.5f * xn * (1.f + erff(xn * 0.70710678118654752f));
        __syncthreads();

        u64 a2 = 0ull;
#pragma unroll 8
        for (int k2 = 0; k2 < 48; k2++) {
            u64 rv = *(const u64*)(row + 2*k2);
            u64 wv = *(const u64*)(ws + tid*98 + 2*k2);
            a2 = ffma2(rv, wv, a2);
        }
        float2 f = unpack2(a2);
        kv[(size_t)r*CC + tid] = f.x + f.y;
    }
}

// ---------------- attention inner: 2 q/thread, padded to 344 kv, m4 unroll 2 ----------------
__device__ __forceinline__ void attn_inner2(
    const float* __restrict__ qp0, const float* __restrict__ qp1,
    const float* KT, const float4* V4,
    float* __restrict__ op0, float* __restrict__ op1)
{
    u64 qd0[16], qd1[16];
#pragma unroll
    for (int i = 0; i < 4; i++) {
        float4 a = *(const float4*)(qp0 + 4*i);
        float4 b = *(const float4*)(qp1 + 4*i);
        qd0[4*i+0] = pack2(a.x*QSCALE, a.x*QSCALE);
        qd0[4*i+1] = pack2(a.y*QSCALE, a.y*QSCALE);
        qd0[4*i+2] = pack2(a.z*QSCALE, a.z*QSCALE);
        qd0[4*i+3] = pack2(a.w*QSCALE, a.w*QSCALE);
        qd1[4*i+0] = pack2(b.x*QSCALE, b.x*QSCALE);
        qd1[4*i+1] = pack2(b.y*QSCALE, b.y*QSCALE);
        qd1[4*i+2] = pack2(b.z*QSCALE, b.z*QSCALE);
        qd1[4*i+3] = pack2(b.w*QSCALE, b.w*QSCALE);
    }
    u64 acc0[8], acc1[8];
#pragma unroll
    for (int i = 0; i < 8; i++) { acc0[i] = 0ull; acc1[i] = 0ull; }
    u64 l0 = 0ull, l1 = 0ull;

#pragma unroll 2
    for (int m4 = 0; m4 < 86; m4++) {      // 344 kvs incl. 1 zero pad
        u64 sa01 = 0ull, sa23 = 0ull, sb01 = 0ull, sb23 = 0ull;
#pragma unroll
        for (int d = 0; d < 16; d++) {
            double2 kk = *(const double2*)(KT + d*352 + m4*4);
            u64 kx = D2U(kk.x), ky = D2U(kk.y);
            sa01 = ffma2(qd0[d], kx, sa01);
            sa23 = ffma2(qd0[d], ky, sa23);
            sb01 = ffma2(qd1[d], kx, sb01);
            sb23 = ffma2(qd1[d], ky, sb23);
        }
        float2 fa01 = unpack2(sa01), fa23 = unpack2(sa23);
        float2 fb01 = unpack2(sb01), fb23 = unpack2(sb23);
        float pa[4] = {ex2f(fa01.x), ex2f(fa01.y), ex2f(fa23.x), ex2f(fa23.y)};
        float pb[4] = {ex2f(fb01.x), ex2f(fb01.y), ex2f(fb23.x), ex2f(fb23.y)};
        l0 = fadd2(l0, pack2(pa[0]+pa[2], pa[1]+pa[3]));
        l1 = fadd2(l1, pack2(pb[0]+pb[2], pb[1]+pb[3]));
#pragma unroll
        for (int jj = 0; jj < 4; jj++) {
            const double2* vp = (const double2*)(V4 + (m4*4 + jj)*4);
            double2 va = vp[0], vb = vp[1], vc = vp[2], vd2 = vp[3];
            u64 pda = pack2(pa[jj], pa[jj]);
            u64 pdb = pack2(pb[jj], pb[jj]);
            acc0[0] = ffma2(pda, D2U(va.x), acc0[0]);
            acc0[1] = ffma2(pda, D2U(va.y), acc0[1]);
            acc0[2] = ffma2(pda, D2U(vb.x), acc0[2]);
            acc0[3] = ffma2(pda, D2U(vb.y), acc0[3]);
            acc0[4] = ffma2(pda, D2U(vc.x), acc0[4]);
            acc0[5] = ffma2(pda, D2U(vc.y), acc0[5]);
            acc0[6] = ffma2(pda, D2U(vd2.x), acc0[6]);
            acc0[7] = ffma2(pda, D2U(vd2.y), acc0[7]);
            acc1[0] = ffma2(pdb, D2U(va.x), acc1[0]);
            acc1[1] = ffma2(pdb, D2U(va.y), acc1[1]);
            acc1[2] = ffma2(pdb, D2U(vb.x), acc1[2]);
            acc1[3] = ffma2(pdb, D2U(vb.y), acc1[3]);
            acc1[4] = ffma2(pdb, D2U(vc.x), acc1[4]);
            acc1[5] = ffma2(pdb, D2U(vc.y), acc1[5]);
            acc1[6] = ffma2(pdb, D2U(vd2.x), acc1[6]);
            acc1[7] = ffma2(pdb, D2U(vd2.y), acc1[7]);
        }
    }
    // pad row contributed exactly p=1 to each l: subtract.
    float2 lf0 = unpack2(l0), lf1 = unpack2(l1);
    float inv0 = 1.f / (lf0.x + lf0.y - 1.f);
    float inv1 = 1.f / (lf1.x + lf1.y - 1.f);
#pragma unroll
    for (int i = 0; i < 4; i++) {
        float2 f0 = unpack2(acc0[2*i]), f1 = unpack2(acc0[2*i+1]);
        *(float4*)(op0 + 4*i) = make_float4(f0.x*inv0, f0.y*inv0, f1.x*inv0, f1.y*inv0);
    }
#pragma unroll
    for (int i = 0; i < 4; i++) {
        float2 f0 = unpack2(acc1[2*i]), f1 = unpack2(acc1[2*i+1]);
        *(float4*)(op1 + 4*i) = make_float4(f0.x*inv1, f0.y*inv1, f1.x*inv1, f1.y*inv1);
    }
}

// ---------------- branch-1 attention (128 thr, 2q each) ----------------
__global__ __launch_bounds__(128, 3) void attn1_kernel(
    const float* __restrict__ q12, const float* __restrict__ kv1,
    float* __restrict__ xcat)
{
    __shared__ float  KT[16*352];
    __shared__ float4 V4[344*4];
    const int bh = blockIdx.y;
    const int b = bh / NH2, h = bh % NH2;
    const int tid = threadIdx.x;

    const float* kvb = kv1 + (size_t)b*NSR*CC + h*16;
    for (int i = tid; i < 344*4; i += 128) {
        int m = i >> 2, d4 = (i & 3) * 4;
        float4 kk = make_float4(0.f, 0.f, 0.f, 0.f);
        float4 vv = make_float4(0.f, 0.f, 0.f, 0.f);
        if (m < NSR) {
            kk = *(const float4*)(kvb + (size_t)m*CC + d4);
            vv = *(const float4*)(kvb + (size_t)m*CC + 48 + d4);
        }
        KT[(d4+0)*352 + m] = kk.x;
        KT[(d4+1)*352 + m] = kk.y;
        KT[(d4+2)*352 + m] = kk.z;
        KT[(d4+3)*352 + m] = kk.w;
        V4[m*4 + (d4>>2)] = vv;
    }
    __syncthreads();

    int n0 = blockIdx.x*256 + tid;
    int n1 = n0 + 128;
    if (n0 >= NN) return;
    if (n1 >= NN) n1 = n0;
    const float* qp0 = q12 + ((size_t)b*NN + n0)*CC + h*16;
    const float* qp1 = q12 + ((size_t)b*NN + n1)*CC + h*16;
    float* op0 = xcat + ((size_t)b*NN + n0)*CC + h*16;
    float* op1 = xcat + ((size_t)b*NN + n1)*CC + h*16;
    attn_inner2(qp0, qp1, KT, V4, op0, op1);
}

// ---------------- branch-2 windowed attention (192 thr, 3 blocks/SM) ----------------
__global__ __launch_bounds__(192, 3) void attn2_kernel(
    const float* __restrict__ q12, const float* __restrict__ kv2,
    float* __restrict__ xcat)
{
    __shared__ float  KT[16*352];
    __shared__ float4 V4[344*4];
    __shared__ int    ns[WT];
    const int blk = blockIdx.x;
    const int w = blk & 63;
    const int bh = blk >> 6;
    const int b = bh / NH2, h = bh % NH2;
    const int wh = w >> 4, ww = (w >> 2) & 3, wd = w & 3;
    const int tid = threadIdx.x;

    for (int j = tid; j < WT; j += 192) {
        int th = j / 49, tw = (j / 7) % 7, td = j % 7;
        ns[j] = (wh*7 + th)*784 + (ww*7 + tw)*28 + (wd*7 + td);
    }
    __syncthreads();
    for (int i = tid; i < 344*4; i += 192) {
        int m = i >> 2, d4 = (i & 3) * 4;
        float4 kk = make_float4(0.f, 0.f, 0.f, 0.f);
        float4 vv = make_float4(0.f, 0.f, 0.f, 0.f);
        if (m < WT) {
            const float* kr = kv2 + ((size_t)b*NN + ns[m])*CC + h*16;
            kk = *(const float4*)(kr + d4);
            vv = *(const float4*)(kr + 48 + d4);
        }
        KT[(d4+0)*352 + m] = kk.x;
        KT[(d4+1)*352 + m] = kk.y;
        KT[(d4+2)*352 + m] = kk.z;
        KT[(d4+3)*352 + m] = kk.w;
        V4[m*4 + (d4>>2)] = vv;
    }
    __syncthreads();

    int t0 = tid;
    if (t0 >= WT) return;
    int t1 = tid + 176;
    if (t1 >= WT) t1 = t0;
    int n0 = ns[t0], n1 = ns[t1];
    const float* qp0 = q12 + ((size_t)b*NN + n0)*CC + 48 + h*16;
    const float* qp1 = q12 + ((size_t)b*NN + n1)*CC + 48 + h*16;
    float* op0 = xcat + ((size_t)b*NN + n0)*CC + 48 + h*16;
    float* op1 = xcat + ((size_t)b*NN + n1)*CC + 48 + h*16;
    attn_inner2(qp0, qp1, KT, V4, op0, op1);
}

// ---------------- streams/events ----------------
struct StreamPack {
    cudaStream_t s1, s2, s3;
    cudaEvent_t ef, e_x3, e_kv1, e_lepe, e_attn2;
    StreamPack() {
        cudaStreamCreateWithFlags(&s1, cudaStreamNonBlocking);
        cudaStreamCreateWithFlags(&s2, cudaStreamNonBlocking);
        cudaStreamCreateWithFlags(&s3, cudaStreamNonBlocking);
        cudaEventCreateWithFlags(&ef,      cudaEventDisableTiming);
        cudaEventCreateWithFlags(&e_x3,    cudaEventDisableTiming);
        cudaEventCreateWithFlags(&e_kv1,   cudaEventDisableTiming);
        cudaEventCreateWithFlags(&e_lepe,  cudaEventDisableTiming);
        cudaEventCreateWithFlags(&e_attn2, cudaEventDisableTiming);
    }
};
static StreamPack SP;

// ---------------- host launch ----------------
extern "C" void kernel_launch(void* const* d_in, const int* in_sizes, int n_in,
                              void* d_out, int out_size)
{
    const int base = n_in - 14;
    const float* x          = (const float*)d_in[0];
    const float* lepe_lin_w = (const float*)d_in[base + 0];
    const float* lepe_lin_b = (const float*)d_in[base + 1];
    const float* lepe_conv_w= (const float*)d_in[base + 2];
    const float* lepe_conv_b= (const float*)d_in[base + 3];
    const float* sr_w       = (const float*)d_in[base + 4];
    const float* sr_b       = (const float*)d_in[base + 5];
    const float* norm_g     = (const float*)d_in[base + 6];
    const float* norm_b     = (const float*)d_in[base + 7];
    const float* q1_w       = (const float*)d_in[base + 8];
    const float* kv1_w      = (const float*)d_in[base + 9];
    const float* q2_w       = (const float*)d_in[base + 10];
    const float* kv2_w      = (const float*)d_in[base + 11];
    const float* proj_w     = (const float*)d_in[base + 12];
    const float* proj_b     = (const float*)d_in[base + 13];
    float* out = (float*)d_out;

    float *p_t, *p_lepe, *p_q12, *p_kv2, *p_xs, *p_kv1, *p_xcat;
    float2* p_wtp;
    cudaGetSymbolAddress((void**)&p_t,    g_t);
    cudaGetSymbolAddress((void**)&p_lepe, g_lepe);
    cudaGetSymbolAddress((void**)&p_q12,  g_q12);
    cudaGetSymbolAddress((void**)&p_kv2,  g_kv2);
    cudaGetSymbolAddress((void**)&p_xs,   g_xs);
    cudaGetSymbolAddress((void**)&p_kv1,  g_kv1);
    cudaGetSymbolAddress((void**)&p_xcat, g_xcat);
    cudaGetSymbolAddress((void**)&p_wtp,  g_wtp);

    const int smemG  = 64*CC*4 + 24*100*16;      // 62976
    const int smemSR = 32*CC*4 + 48*49*16;       // 12288 + 37632 = 49920
    cudaFuncSetAttribute(gemm_x3_kernel,   cudaFuncAttributeMaxDynamicSharedMemorySize, smemG);
    cudaFuncSetAttribute(gemm_proj_kernel, cudaFuncAttributeMaxDynamicSharedMemorySize, smemG);
    cudaFuncSetAttribute(sr_conv_kernel,   cudaFuncAttributeMaxDynamicSharedMemorySize, smemSR);

    const int gM = BNr / 64;   // 686
    cudaStream_t s0 = 0;

    cudaEventRecord(SP.ef, s0);
    cudaStreamWaitEvent(SP.s1, SP.ef, 0);
    cudaStreamWaitEvent(SP.s2, SP.ef, 0);
    cudaStreamWaitEvent(SP.s3, SP.ef, 0);

    // s0: fused x projections (t, q12, kv2)
    gemm_x3_kernel<<<gM, 256, smemG, s0>>>(x, lepe_lin_w, lepe_lin_b, q1_w, q2_w, kv2_w,
                                           p_t, p_q12, p_kv2);
    cudaEventRecord(SP.e_x3, s0);

    // s1: lepe conv after x3
    cudaStreamWaitEvent(SP.s1, SP.e_x3, 0);
    lepe_conv_kernel<<<dim3(BB*343, 4), 192, 0, SP.s1>>>(p_t, lepe_conv_w, lepe_conv_b, p_lepe);
    cudaEventRecord(SP.e_lepe, SP.s1);

    // s2: SR chain -> kv1
    sr_pack_init_kernel<<<(64*48*CC + 255)/256, 256, 0, SP.s2>>>(sr_w, sr_b, p_wtp, p_xs);
    sr_conv_kernel<<<dim3((BB*NSR + 31)/32, 16), 128, smemSR, SP.s2>>>(x, p_wtp, p_xs);
    ln_gelu_kv1_kernel<<<(BB*NSR + 3)/4, 96, 0, SP.s2>>>(p_xs, norm_g, norm_b, kv1_w, p_kv1);
    cudaEventRecord(SP.e_kv1, SP.s2);

    // s3: attn2 after x3
    cudaStreamWaitEvent(SP.s3, SP.e_x3, 0);
    attn2_kernel<<<BB*NH2*NWIN, 192, 0, SP.s3>>>(p_q12, p_kv2, p_xcat);
    cudaEventRecord(SP.e_attn2, SP.s3);

    // s0: attn1 after kv1 (q12 ordered on s0)
    cudaStreamWaitEvent(s0, SP.e_kv1, 0);
    attn1_kernel<<<dim3((NN + 255)/256, BB*NH2), 128, 0, s0>>>(p_q12, p_kv1, p_xcat);

    // join
    cudaStreamWaitEvent(s0, SP.e_attn2, 0);
    cudaStreamWaitEvent(s0, SP.e_lepe, 0);
    gemm_proj_kernel<<<gM, 256, smemG, s0>>>(p_xcat, p_lepe, proj_w, proj_b, out);
}

// round 16
// speedup vs baseline: 1.0112x; 1.0112x over previous
#include <cuda_runtime.h>
#include <math.h>

// ---------------- problem constants (fixed shapes) ----------------
#define BB   2
#define NN   21952          // 28^3
#define CC   96
#define BNr  43904          // BB*NN
#define NH2  3
#define NSR  343            // 7^3
#define WT   343
#define NWIN 64

typedef unsigned long long u64;

__device__ __forceinline__ u64 ffma2(u64 a, u64 b, u64 c) {
    u64 d; asm("fma.rn.f32x2 %0,%1,%2,%3;" : "=l"(d) : "l"(a), "l"(b), "l"(c)); return d;
}
__device__ __forceinline__ u64 fadd2(u64 a, u64 b) {
    u64 d; asm("add.rn.f32x2 %0,%1,%2;" : "=l"(d) : "l"(a), "l"(b)); return d;
}
__device__ __forceinline__ u64 pack2(float x, float y) {
    u64 d; asm("mov.b64 %0,{%1,%2};" : "=l"(d) : "f"(x), "f"(y)); return d;
}
__device__ __forceinline__ float2 unpack2(u64 a) {
    float2 f; asm("mov.b64 {%0,%1},%2;" : "=f"(f.x), "=f"(f.y) : "l"(a)); return f;
}
__device__ __forceinline__ float ex2f(float x) {
    float r; asm("ex2.approx.f32 %0, %1;" : "=f"(r) : "f"(x)); return r;
}
#define D2U(x) __double_as_longlong(x)
#define QSCALE (0.25f * 1.4426950408889634f)

// ---------------- device scratch ----------------
__device__ float  g_t   [BNr*CC];
__device__ float  g_lepe[BNr*CC];
__device__ float  g_q12 [BNr*CC];
__device__ float  g_kv2 [BNr*CC];
__device__ float  g_xs  [BB*NSR*CC];
__device__ float  g_kv1 [BB*NSR*CC];
__device__ float  g_xcat[BNr*CC];
__device__ float2 g_wtp [64*48*CC];

// ---------------- fused x-projections: t (bias), q12, kv2 in one kernel ----------------
__global__ __launch_bounds__(256) void gemm_x3_kernel(
    const float* __restrict__ x,
    const float* __restrict__ lepe_lin_w, const float* __restrict__ lepe_lin_b,
    const float* __restrict__ q1_w, const float* __restrict__ q2_w,
    const float* __restrict__ kv2_w,
    float* __restrict__ t_out, float* __restrict__ q12_out, float* __restrict__ kv2_out)
{
    extern __shared__ float sm[];
    float*  As = sm;                        // [64][96]
    float4* Wq = (float4*)(sm + 64*CC);     // [24][100]
    const int tid = threadIdx.x;
    const int m0  = blockIdx.x * 64;

    for (int i = tid; i < 64*CC; i += 256)
        As[i] = x[(size_t)m0*CC + i];

    const int ty = tid >> 4, tx = tid & 15;
    const int mb = ty*4;

#pragma unroll
    for (int pass = 0; pass < 3; pass++) {
        for (int i = tid; i < 24*CC; i += 256) {
            int k4 = i / CC, j = i - k4*CC;
            const float* Wr;
            if (pass == 0)      Wr = lepe_lin_w + (size_t)j*CC;
            else if (pass == 1) Wr = (j < 48) ? (q1_w + (size_t)j*CC) : (q2_w + (size_t)(j-48)*CC);
            else                Wr = kv2_w + (size_t)j*CC;
            Wq[k4*100 + j] = *(const float4*)(Wr + 4*k4);
        }
        __syncthreads();

        u64 acc[4][6];
#pragma unroll
        for (int r = 0; r < 4; r++)
#pragma unroll
            for (int j = 0; j < 6; j++) acc[r][j] = 0ull;

#pragma unroll 4
        for (int k4 = 0; k4 < 24; k4++) {
            double2 a[4];
#pragma unroll
            for (int r = 0; r < 4; r++) a[r] = *(const double2*)(As + (mb+r)*CC + k4*4);
            double2 w[6];
#pragma unroll
            for (int j = 0; j < 6; j++) w[j] = *(const double2*)(Wq + k4*100 + tx + 16*j);
#pragma unroll
            for (int r = 0; r < 4; r++)
#pragma unroll
                for (int j = 0; j < 6; j++) {
                    acc[r][j] = ffma2(D2U(a[r].x), D2U(w[j].x), acc[r][j]);
                    acc[r][j] = ffma2(D2U(a[r].y), D2U(w[j].y), acc[r][j]);
                }
        }

        float* outp = (pass == 0) ? t_out : (pass == 1 ? q12_out : kv2_out);
#pragma unroll
        for (int r = 0; r < 4; r++) {
            int gr = m0 + mb + r;
#pragma unroll
            for (int j = 0; j < 6; j++) {
                int col = tx + 16*j;
                float2 f = unpack2(acc[r][j]);
                float o = f.x + f.y;
                if (pass == 0) o += lepe_lin_b[col];
                outp[(size_t)gr*CC + col] = o;
            }
        }
        __syncthreads();
    }
}

// ---------------- f32x2 GEMM (proj: xcat+lepe -> out) ----------------
__global__ __launch_bounds__(256) void gemm_proj_kernel(
    const float* __restrict__ A, const float* __restrict__ A2,
    const float* __restrict__ W1, const float* __restrict__ bias,
    float* __restrict__ out)
{
    extern __shared__ float sm[];
    float*  As = sm;
    float4* Wq = (float4*)(sm + 64*CC);
    const int tid = threadIdx.x;
    const int m0  = blockIdx.x * 64;

    for (int i = tid; i < 64*CC; i += 256)
        As[i] = A[(size_t)m0*CC + i] + A2[(size_t)m0*CC + i];
    for (int i = tid; i < 24*CC; i += 256) {
        int k4 = i / CC, j = i - k4*CC;
        Wq[k4*100 + j] = *(const float4*)(W1 + (size_t)j*CC + 4*k4);
    }
    __syncthreads();

    const int ty = tid >> 4, tx = tid & 15;
    const int mb = ty*4;
    u64 acc[4][6];
#pragma unroll
    for (int r = 0; r < 4; r++)
#pragma unroll
        for (int j = 0; j < 6; j++) acc[r][j] = 0ull;

#pragma unroll 4
    for (int k4 = 0; k4 < 24; k4++) {
        double2 a[4];
#pragma unroll
        for (int r = 0; r < 4; r++) a[r] = *(const double2*)(As + (mb+r)*CC + k4*4);
        double2 w[6];
#pragma unroll
        for (int j = 0; j < 6; j++) w[j] = *(const double2*)(Wq + k4*100 + tx + 16*j);
#pragma unroll
        for (int r = 0; r < 4; r++)
#pragma unroll
            for (int j = 0; j < 6; j++) {
                acc[r][j] = ffma2(D2U(a[r].x), D2U(w[j].x), acc[r][j]);
                acc[r][j] = ffma2(D2U(a[r].y), D2U(w[j].y), acc[r][j]);
            }
    }

#pragma unroll
    for (int r = 0; r < 4; r++) {
        int gr = m0 + mb + r;
#pragma unroll
        for (int j = 0; j < 6; j++) {
            int col = tx + 16*j;
            float2 f = unpack2(acc[r][j]);
            out[(size_t)gr*CC + col] = f.x + f.y + bias[col];
        }
    }
}

// ---------------- LePE depthwise 3x3x3 ----------------
__global__ __launch_bounds__(192) void lepe_conv_kernel(
    const float* __restrict__ tin, const float* __restrict__ cw,
    const float* __restrict__ cb, float* __restrict__ out)
{
    __shared__ float st [216*24];
    __shared__ float wst[27*24];
    const int tid = threadIdx.x;
    const int b = blockIdx.x / 343;
    const int t = blockIdx.x % 343;
    const int c0 = blockIdx.y * 24;
    const int th = t / 49, tw = (t / 7) % 7, td = t % 7;
    const int h0 = th*4 - 1, w0 = tw*4 - 1, d0 = td*4 - 1;

    for (int i = tid; i < 216*6; i += 192) {
        int hv = i / 6, cq = (i - hv*6) * 4;
        int lz = hv / 36, ly = (hv / 6) % 6, lx = hv % 6;
        int gz = h0 + lz, gy = w0 + ly, gx = d0 + lx;
        float4 v = make_float4(0.f, 0.f, 0.f, 0.f);
        if ((unsigned)gz < 28u && (unsigned)gy < 28u && (unsigned)gx < 28u)
            v = *(const float4*)(tin + ((size_t)b*NN + gz*784 + gy*28 + gx)*CC + c0 + cq);
        *(float4*)(st + hv*24 + cq) = v;
    }
    for (int i = tid; i < 27*24; i += 192) {
        int cl = i / 27, j = i - cl*27;
        wst[j*24 + cl] = cw[(c0 + cl)*27 + j];
    }
    __syncthreads();

    const int half = tid / 96;
    const int t96 = tid - half*96;
    const int hw = t96 / 6;
    const int c4 = (t96 - hw*6) * 4;
    const int lh = hw >> 2, lw = hw & 3;
    const int dbase = half*2;

    u64 acc[2][2];
    {
        double2 cbv = *(const double2*)(cb + c0 + c4);
#pragma unroll
        for (int v = 0; v < 2; v++) { acc[v][0] = D2U(cbv.x); acc[v][1] = D2U(cbv.y); }
    }

#pragma unroll
    for (int jz = 0; jz < 3; jz++)
#pragma unroll
        for (int jy = 0; jy < 3; jy++) {
            const int base = (lh + jz)*36 + (lw + jy)*6 + dbase;
            double2 col[4];
#pragma unroll
            for (int dd = 0; dd < 4; dd++) col[dd] = *(const double2*)(st + (base + dd)*24 + c4);
#pragma unroll
            for (int jx = 0; jx < 3; jx++) {
                double2 wv = *(const double2*)(wst + (jz*9 + jy*3 + jx)*24 + c4);
                u64 w0v = D2U(wv.x), w1v = D2U(wv.y);
#pragma unroll
                for (int vd = 0; vd < 2; vd++) {
                    acc[vd][0] = ffma2(D2U(col[vd+jx].x), w0v, acc[vd][0]);
                    acc[vd][1] = ffma2(D2U(col[vd+jx].y), w1v, acc[vd][1]);
                }
            }
        }

#pragma unroll
    for (int vd = 0; vd < 2; vd++) {
        int n = (th*4 + lh)*784 + (tw*4 + lw)*28 + (td*4 + dbase + vd);
        float2 f0 = unpack2(acc[vd][0]), f1 = unpack2(acc[vd][1]);
        *(float4*)(out + ((size_t)b*NN + n)*CC + c0 + c4) = make_float4(f0.x, f0.y, f1.x, f1.y);
    }
}

// ---------------- pack SR weights (coalesced) + init xs with bias ----------------
__global__ __launch_bounds__(256) void sr_pack_init_kernel(
    const float* __restrict__ w, const float* __restrict__ srb,
    float2* __restrict__ wtp, float* __restrict__ xs)
{
    int i = blockIdx.x * 256 + threadIdx.x;
    if (i < 64*48*CC) {
        int v = i & 63;
        int rem = i >> 6;
        int j = rem % CC;
        int k2 = rem / CC;
        float a = w[((size_t)j*CC + 2*k2  )*64 + v];
        float b = w[((size_t)j*CC + 2*k2+1)*64 + v];
        wtp[(size_t)v*48*CC + k2*CC + j] = make_float2(a, b);
    }
    if (i < BB*NSR*CC) xs[i] = srb[i % CC];
}

// ---------------- SR conv: 32-row tile, 2 voxels/block (measured best) ----------------
__global__ __launch_bounds__(256) void sr_conv_kernel(
    const float* __restrict__ x, const float2* __restrict__ wtp,
    float* __restrict__ xs)
{
    extern __shared__ float sm[];
    float*  As  = sm;                       // [32][96]
    float4* Wp4 = (float4*)(sm + 32*CC);    // [48][49] float4
    const int tid = threadIdx.x;
    const int m0 = blockIdx.x * 32;
    const int v0 = blockIdx.y * 2;
    const int ty = tid >> 4, tx = tid & 15;
    const int mb = ty*2;

    const int r8 = tid >> 3;       // 0..31
    const int l8 = tid & 7;        // 0..7 (12 floats each)
    const int gr8 = m0 + r8;
    const float* xrow = x;
    int hh4 = 0, ww4 = 0, dd4 = 0;
    const bool valid = gr8 < BB*NSR;
    if (valid) {
        int b = gr8 / NSR, p = gr8 - b*NSR;
        int ph = p / 49, pr = p - ph*49;
        int pw = pr / 7, pd = pr - pw*7;
        xrow = x + (size_t)b*NN*CC;
        hh4 = 4*ph; ww4 = 4*pw; dd4 = 4*pd;
    }

    u64 acc[2][6];
#pragma unroll
    for (int r = 0; r < 2; r++)
#pragma unroll
        for (int j = 0; j < 6; j++) acc[r][j] = 0ull;

    for (int vv = 0; vv < 2; vv++) {
        const int v = v0 + vv;
        const int kh = v >> 4, kw = (v >> 2) & 3, kd = v & 3;

        {
            float4* dst = (float4*)(As + r8*CC + l8*12);
            if (valid) {
                const float* src = xrow + ((size_t)((hh4+kh)*784 + (ww4+kw)*28 + (dd4+kd)))*CC + l8*12;
                dst[0] = *(const float4*)(src);
                dst[1] = *(const float4*)(src + 4);
                dst[2] = *(const float4*)(src + 8);
            } else {
                float4 z = make_float4(0.f,0.f,0.f,0.f);
                dst[0] = z; dst[1] = z; dst[2] = z;
            }
        }
        for (int i = tid; i < 48*48; i += 256) {
            int k2 = i / 48, j4 = i - k2*48;
            Wp4[k2*49 + j4] = *(const float4*)(&wtp[(size_t)v*48*CC + k2*CC + 2*j4]);
        }
        __syncthreads();

#pragma unroll 2
        for (int k4 = 0; k4 < 24; k4++) {
            double2 a0 = *(const double2*)(As + (mb+0)*CC + k4*4);
            double2 a1 = *(const double2*)(As + (mb+1)*CC + k4*4);
            const float4* wra = Wp4 + (2*k4  )*49 + tx*3;
            const float4* wrb = Wp4 + (2*k4+1)*49 + tx*3;
#pragma unroll
            for (int jj = 0; jj < 3; jj++) {
                float4 wa = wra[jj];
                float4 wb = wrb[jj];
                u64 wa0 = ((const u64*)&wa)[0], wa1 = ((const u64*)&wa)[1];
                u64 wb0 = ((const u64*)&wb)[0], wb1 = ((const u64*)&wb)[1];
                acc[0][jj*2+0] = ffma2(D2U(a0.x), wa0, acc[0][jj*2+0]);
                acc[0][jj*2+1] = ffma2(D2U(a0.x), wa1, acc[0][jj*2+1]);
                acc[1][jj*2+0] = ffma2(D2U(a1.x), wa0, acc[1][jj*2+0]);
                acc[1][jj*2+1] = ffma2(D2U(a1.x), wa1, acc[1][jj*2+1]);
                acc[0][jj*2+0] = ffma2(D2U(a0.y), wb0, acc[0][jj*2+0]);
                acc[0][jj*2+1] = ffma2(D2U(a0.y), wb1, acc[0][jj*2+1]);
                acc[1][jj*2+0] = ffma2(D2U(a1.y), wb0, acc[1][jj*2+0]);
                acc[1][jj*2+1] = ffma2(D2U(a1.y), wb1, acc[1][jj*2+1]);
            }
        }
        __syncthreads();
    }

#pragma unroll
    for (int r = 0; r < 2; r++) {
        int gr = m0 + mb + r;
        if (gr >= BB*NSR) continue;
#pragma unroll
        for (int j = 0; j < 6; j++) {
            float2 f = unpack2(acc[r][j]);
            atomicAdd(&xs[(size_t)gr*CC + tx*6 + j], f.x + f.y);
        }
    }
}

// ---------------- LayerNorm + GELU + kv1 GEMM (4 rows / block) ----------------
__global__ __launch_bounds__(96) void ln_gelu_kv1_kernel(
    const float* __restrict__ xs, const float* __restrict__ gg,
    const float* __restrict__ bb, const float* __restrict__ w,
    float* __restrict__ kv)
{
    __shared__ float ws[CC*98];
    __shared__ float row[CC];
    __shared__ float rs[3], rs2[3];
    const int tid = threadIdx.x;

    for (int i = tid; i < CC*CC; i += 96)
        ws[(i / CC)*98 + (i % CC)] = w[i];

    for (int rr = 0; rr < 4; rr++) {
        int r = blockIdx.x*4 + rr;
        if (r >= BB*NSR) break;
        __syncthreads();
        float v = xs[(size_t)r*CC + tid];
        float s = v, s2 = v*v;
#pragma unroll
        for (int o = 16; o; o >>= 1) {
            s  += __shfl_xor_sync(0xffffffffu, s, o);
            s2 += __shfl_xor_sync(0xffffffffu, s2, o);
        }
        if ((tid & 31) == 0) { rs[tid >> 5] = s; rs2[tid >> 5] = s2; }
        __syncthreads();
        float mean = (rs[0] + rs[1] + rs[2]) * (1.f/96.f);
        float var  = (rs2[0] + rs2[1] + rs2[2]) * (1.f/96.f) - mean*mean;
        float xn = (v - mean) * rsqrtf(var + 1e-5f) * gg[tid] + bb[tid];
        row[tid] = 0.5f * xn * (1.f + erff(xn * 0.70710678118654752f));
        __syncthreads();

        u64 a2 = 0ull;
#pragma unroll 8
        for (int k2 = 0; k2 < 48; k2++) {
            u64 rv = *(const u64*)(row + 2*k2);
            u64 wv = *(const u64*)(ws + tid*98 + 2*k2);
            a2 = ffma2(rv, wv, a2);
        }
        float2 f = unpack2(a2);
        kv[(size_t)r*CC + tid] = f.x + f.y;
    }
}

// ---------------- attention inner: 2 q/thread, padded to 344 kv, m4 unroll 2 ----------------
__device__ __forceinline__ void attn_inner2(
    const float* __restrict__ qp0, const float* __restrict__ qp1,
    const float* KT, const float4* V4,
    float* __restrict__ op0, float* __restrict__ op1)
{
    u64 qd0[16], qd1[16];
#pragma unroll
    for (int i = 0; i < 4; i++) {
        float4 a = *(const float4*)(qp0 + 4*i);
        float4 b = *(const float4*)(qp1 + 4*i);
        qd0[4*i+0] = pack2(a.x*QSCALE, a.x*QSCALE);
        qd0[4*i+1] = pack2(a.y*QSCALE, a.y*QSCALE);
        qd0[4*i+2] = pack2(a.z*QSCALE, a.z*QSCALE);
        qd0[4*i+3] = pack2(a.w*QSCALE, a.w*QSCALE);
        qd1[4*i+0] = pack2(b.x*QSCALE, b.x*QSCALE);
        qd1[4*i+1] = pack2(b.y*QSCALE, b.y*QSCALE);
        qd1[4*i+2] = pack2(b.z*QSCALE, b.z*QSCALE);
        qd1[4*i+3] = pack2(b.w*QSCALE, b.w*QSCALE);
    }
    u64 acc0[8], acc1[8];
#pragma unroll
    for (int i = 0; i < 8; i++) { acc0[i] = 0ull; acc1[i] = 0ull; }
    u64 l0 = 0ull, l1 = 0ull;

#pragma unroll 2
    for (int m4 = 0; m4 < 86; m4++) {      // 344 kvs incl. 1 zero pad
        u64 sa01 = 0ull, sa23 = 0ull, sb01 = 0ull, sb23 = 0ull;
#pragma unroll
        for (int d = 0; d < 16; d++) {
            double2 kk = *(const double2*)(KT + d*352 + m4*4);
            u64 kx = D2U(kk.x), ky = D2U(kk.y);
            sa01 = ffma2(qd0[d], kx, sa01);
            sa23 = ffma2(qd0[d], ky, sa23);
            sb01 = ffma2(qd1[d], kx, sb01);
            sb23 = ffma2(qd1[d], ky, sb23);
        }
        float2 fa01 = unpack2(sa01), fa23 = unpack2(sa23);
        float2 fb01 = unpack2(sb01), fb23 = unpack2(sb23);
        float pa[4] = {ex2f(fa01.x), ex2f(fa01.y), ex2f(fa23.x), ex2f(fa23.y)};
        float pb[4] = {ex2f(fb01.x), ex2f(fb01.y), ex2f(fb23.x), ex2f(fb23.y)};
        l0 = fadd2(l0, pack2(pa[0]+pa[2], pa[1]+pa[3]));
        l1 = fadd2(l1, pack2(pb[0]+pb[2], pb[1]+pb[3]));
#pragma unroll
        for (int jj = 0; jj < 4; jj++) {
            const double2* vp = (const double2*)(V4 + (m4*4 + jj)*4);
            double2 va = vp[0], vb = vp[1], vc = vp[2], vd2 = vp[3];
            u64 pda = pack2(pa[jj], pa[jj]);
            u64 pdb = pack2(pb[jj], pb[jj]);
            acc0[0] = ffma2(pda, D2U(va.x), acc0[0]);
            acc0[1] = ffma2(pda, D2U(va.y), acc0[1]);
            acc0[2] = ffma2(pda, D2U(vb.x), acc0[2]);
            acc0[3] = ffma2(pda, D2U(vb.y), acc0[3]);
            acc0[4] = ffma2(pda, D2U(vc.x), acc0[4]);
            acc0[5] = ffma2(pda, D2U(vc.y), acc0[5]);
            acc0[6] = ffma2(pda, D2U(vd2.x), acc0[6]);
            acc0[7] = ffma2(pda, D2U(vd2.y), acc0[7]);
            acc1[0] = ffma2(pdb, D2U(va.x), acc1[0]);
            acc1[1] = ffma2(pdb, D2U(va.y), acc1[1]);
            acc1[2] = ffma2(pdb, D2U(vb.x), acc1[2]);
            acc1[3] = ffma2(pdb, D2U(vb.y), acc1[3]);
            acc1[4] = ffma2(pdb, D2U(vc.x), acc1[4]);
            acc1[5] = ffma2(pdb, D2U(vc.y), acc1[5]);
            acc1[6] = ffma2(pdb, D2U(vd2.x), acc1[6]);
            acc1[7] = ffma2(pdb, D2U(vd2.y), acc1[7]);
        }
    }
    // pad row contributed exactly p=1 to each l: subtract.
    float2 lf0 = unpack2(l0), lf1 = unpack2(l1);
    float inv0 = 1.f / (lf0.x + lf0.y - 1.f);
    float inv1 = 1.f / (lf1.x + lf1.y - 1.f);
#pragma unroll
    for (int i = 0; i < 4; i++) {
        float2 f0 = unpack2(acc0[2*i]), f1 = unpack2(acc0[2*i+1]);
        *(float4*)(op0 + 4*i) = make_float4(f0.x*inv0, f0.y*inv0, f1.x*inv0, f1.y*inv0);
    }
#pragma unroll
    for (int i = 0; i < 4; i++) {
        float2 f0 = unpack2(acc1[2*i]), f1 = unpack2(acc1[2*i+1]);
        *(float4*)(op1 + 4*i) = make_float4(f0.x*inv1, f0.y*inv1, f1.x*inv1, f1.y*inv1);
    }
}

// ---------------- branch-1 attention (128 thr, 2q each) ----------------
__global__ __launch_bounds__(128, 3) void attn1_kernel(
    const float* __restrict__ q12, const float* __restrict__ kv1,
    float* __restrict__ xcat)
{
    __shared__ float  KT[16*352];
    __shared__ float4 V4[344*4];
    const int bh = blockIdx.y;
    const int b = bh / NH2, h = bh % NH2;
    const int tid = threadIdx.x;

    const float* kvb = kv1 + (size_t)b*NSR*CC + h*16;
    for (int i = tid; i < 344*4; i += 128) {
        int m = i >> 2, d4 = (i & 3) * 4;
        float4 kk = make_float4(0.f, 0.f, 0.f, 0.f);
        float4 vv = make_float4(0.f, 0.f, 0.f, 0.f);
        if (m < NSR) {
            kk = *(const float4*)(kvb + (size_t)m*CC + d4);
            vv = *(const float4*)(kvb + (size_t)m*CC + 48 + d4);
        }
        KT[(d4+0)*352 + m] = kk.x;
        KT[(d4+1)*352 + m] = kk.y;
        KT[(d4+2)*352 + m] = kk.z;
        KT[(d4+3)*352 + m] = kk.w;
        V4[m*4 + (d4>>2)] = vv;
    }
    __syncthreads();

    int n0 = blockIdx.x*256 + tid;
    int n1 = n0 + 128;
    if (n0 >= NN) return;
    if (n1 >= NN) n1 = n0;
    const float* qp0 = q12 + ((size_t)b*NN + n0)*CC + h*16;
    const float* qp1 = q12 + ((size_t)b*NN + n1)*CC + h*16;
    float* op0 = xcat + ((size_t)b*NN + n0)*CC + h*16;
    float* op1 = xcat + ((size_t)b*NN + n1)*CC + h*16;
    attn_inner2(qp0, qp1, KT, V4, op0, op1);
}

// ---------------- branch-2 windowed attention (192 thr, 3 blocks/SM) ----------------
__global__ __launch_bounds__(192, 3) void attn2_kernel(
    const float* __restrict__ q12, const float* __restrict__ kv2,
    float* __restrict__ xcat)
{
    __shared__ float  KT[16*352];
    __shared__ float4 V4[344*4];
    __shared__ int    ns[WT];
    const int blk = blockIdx.x;
    const int w = blk & 63;
    const int bh = blk >> 6;
    const int b = bh / NH2, h = bh % NH2;
    const int wh = w >> 4, ww = (w >> 2) & 3, wd = w & 3;
    const int tid = threadIdx.x;

    for (int j = tid; j < WT; j += 192) {
        int th = j / 49, tw = (j / 7) % 7, td = j % 7;
        ns[j] = (wh*7 + th)*784 + (ww*7 + tw)*28 + (wd*7 + td);
    }
    __syncthreads();
    for (int i = tid; i < 344*4; i += 192) {
        int m = i >> 2, d4 = (i & 3) * 4;
        float4 kk = make_float4(0.f, 0.f, 0.f, 0.f);
        float4 vv = make_float4(0.f, 0.f, 0.f, 0.f);
        if (m < WT) {
            const float* kr = kv2 + ((size_t)b*NN + ns[m])*CC + h*16;
            kk = *(const float4*)(kr + d4);
            vv = *(const float4*)(kr + 48 + d4);
        }
        KT[(d4+0)*352 + m] = kk.x;
        KT[(d4+1)*352 + m] = kk.y;
        KT[(d4+2)*352 + m] = kk.z;
        KT[(d4+3)*352 + m] = kk.w;
        V4[m*4 + (d4>>2)] = vv;
    }
    __syncthreads();

    int t0 = tid;
    if (t0 >= WT) return;
    int t1 = tid + 176;
    if (t1 >= WT) t1 = t0;
    int n0 = ns[t0], n1 = ns[t1];
    const float* qp0 = q12 + ((size_t)b*NN + n0)*CC + 48 + h*16;
    const float* qp1 = q12 + ((size_t)b*NN + n1)*CC + 48 + h*16;
    float* op0 = xcat + ((size_t)b*NN + n0)*CC + 48 + h*16;
    float* op1 = xcat + ((size_t)b*NN + n1)*CC + 48 + h*16;
    attn_inner2(qp0, qp1, KT, V4, op0, op1);
}

// ---------------- streams/events ----------------
struct StreamPack {
    cudaStream_t s1, s2, s3;
    cudaEvent_t ef, e_x3, e_kv1, e_lepe, e_attn2;
    StreamPack() {
        cudaStreamCreateWithFlags(&s1, cudaStreamNonBlocking);
        cudaStreamCreateWithFlags(&s2, cudaStreamNonBlocking);
        cudaStreamCreateWithFlags(&s3, cudaStreamNonBlocking);
        cudaEventCreateWithFlags(&ef,      cudaEventDisableTiming);
        cudaEventCreateWithFlags(&e_x3,    cudaEventDisableTiming);
        cudaEventCreateWithFlags(&e_kv1,   cudaEventDisableTiming);
        cudaEventCreateWithFlags(&e_lepe,  cudaEventDisableTiming);
        cudaEventCreateWithFlags(&e_attn2, cudaEventDisableTiming);
    }
};
static StreamPack SP;

// ---------------- host launch ----------------
extern "C" void kernel_launch(void* const* d_in, const int* in_sizes, int n_in,
                              void* d_out, int out_size)
{
    const int base = n_in - 14;
    const float* x          = (const float*)d_in[0];
    const float* lepe_lin_w = (const float*)d_in[base + 0];
    const float* lepe_lin_b = (const float*)d_in[base + 1];
    const float* lepe_conv_w= (const float*)d_in[base + 2];
    const float* lepe_conv_b= (const float*)d_in[base + 3];
    const float* sr_w       = (const float*)d_in[base + 4];
    const float* sr_b       = (const float*)d_in[base + 5];
    const float* norm_g     = (const float*)d_in[base + 6];
    const float* norm_b     = (const float*)d_in[base + 7];
    const float* q1_w       = (const float*)d_in[base + 8];
    const float* kv1_w      = (const float*)d_in[base + 9];
    const float* q2_w       = (const float*)d_in[base + 10];
    const float* kv2_w      = (const float*)d_in[base + 11];
    const float* proj_w     = (const float*)d_in[base + 12];
    const float* proj_b     = (const float*)d_in[base + 13];
    float* out = (float*)d_out;

    float *p_t, *p_lepe, *p_q12, *p_kv2, *p_xs, *p_kv1, *p_xcat;
    float2* p_wtp;
    cudaGetSymbolAddress((void**)&p_t,    g_t);
    cudaGetSymbolAddress((void**)&p_lepe, g_lepe);
    cudaGetSymbolAddress((void**)&p_q12,  g_q12);
    cudaGetSymbolAddress((void**)&p_kv2,  g_kv2);
    cudaGetSymbolAddress((void**)&p_xs,   g_xs);
    cudaGetSymbolAddress((void**)&p_kv1,  g_kv1);
    cudaGetSymbolAddress((void**)&p_xcat, g_xcat);
    cudaGetSymbolAddress((void**)&p_wtp,  g_wtp);

    const int smemG  = 64*CC*4 + 24*100*16;      // 62976
    const int smemSR = 32*CC*4 + 48*49*16;       // 12288 + 37632 = 49920
    cudaFuncSetAttribute(gemm_x3_kernel,   cudaFuncAttributeMaxDynamicSharedMemorySize, smemG);
    cudaFuncSetAttribute(gemm_proj_kernel, cudaFuncAttributeMaxDynamicSharedMemorySize, smemG);
    cudaFuncSetAttribute(sr_conv_kernel,   cudaFuncAttributeMaxDynamicSharedMemorySize, smemSR);

    const int gM = BNr / 64;   // 686
    cudaStream_t s0 = 0;

    cudaEventRecord(SP.ef, s0);
    cudaStreamWaitEvent(SP.s1, SP.ef, 0);
    cudaStreamWaitEvent(SP.s2, SP.ef, 0);
    cudaStreamWaitEvent(SP.s3, SP.ef, 0);

    // s0: fused x projections (t, q12, kv2)
    gemm_x3_kernel<<<gM, 256, smemG, s0>>>(x, lepe_lin_w, lepe_lin_b, q1_w, q2_w, kv2_w,
                                           p_t, p_q12, p_kv2);
    cudaEventRecord(SP.e_x3, s0);

    // s1: lepe conv after x3
    cudaStreamWaitEvent(SP.s1, SP.e_x3, 0);
    lepe_conv_kernel<<<dim3(BB*343, 4), 192, 0, SP.s1>>>(p_t, lepe_conv_w, lepe_conv_b, p_lepe);
    cudaEventRecord(SP.e_lepe, SP.s1);

    // s2: SR chain -> kv1
    sr_pack_init_kernel<<<(64*48*CC + 255)/256, 256, 0, SP.s2>>>(sr_w, sr_b, p_wtp, p_xs);
    sr_conv_kernel<<<dim3((BB*NSR + 31)/32, 32), 256, smemSR, SP.s2>>>(x, p_wtp, p_xs);
    ln_gelu_kv1_kernel<<<(BB*NSR + 3)/4, 96, 0, SP.s2>>>(p_xs, norm_g, norm_b, kv1_w, p_kv1);
    cudaEventRecord(SP.e_kv1, SP.s2);

    // s3: attn2 after x3
    cudaStreamWaitEvent(SP.s3, SP.e_x3, 0);
    attn2_kernel<<<BB*NH2*NWIN, 192, 0, SP.s3>>>(p_q12, p_kv2, p_xcat);
    cudaEventRecord(SP.e_attn2, SP.s3);

    // s0: attn1 after kv1 (q12 ordered on s0)
    cudaStreamWaitEvent(s0, SP.e_kv1, 0);
    attn1_kernel<<<dim3((NN + 255)/256, BB*NH2), 128, 0, s0>>>(p_q12, p_kv1, p_xcat);

    // join
    cudaStreamWaitEvent(s0, SP.e_attn2, 0);
    cudaStreamWaitEvent(s0, SP.e_lepe, 0);
    gemm_proj_kernel<<<gM, 256, smemG, s0>>>(p_xcat, p_lepe, proj_w, proj_b, out);
}